// round 12
// baseline (speedup 1.0000x reference)
#include <cuda_runtime.h>
#include <math.h>
#include <stdint.h>

// ---------------- problem constants ----------------
#define B 32
#define S 512
#define H 512
#define NH 8
#define DH 64
#define INNER 2048
#define BS (B*S)            // 16384
#define BSH ((size_t)B*S*H) // 8388608

// ---------------- scratch ----------------
__device__ float g_Q  [BSH];
__device__ float g_K  [BSH];
__device__ float g_V  [BSH];
__device__ float g_HK [BSH];   // 0.5*(bhk + pk)
__device__ float g_QH [BSH];   // 0.5*(bhq + pq)
__device__ float g_PK [S*H];
__device__ float g_PQ [S*H];
__device__ float g_CTX[BSH];
__device__ float g_ATT[BSH];
__device__ float g_AO [BSH];
__device__ float g_H1 [(size_t)BS*INNER];
__device__ float g_WT [4194304];   // tf32 weights pool
__device__ float g_BQK[1024];      // packed bq|bk
__device__ float g_BB2[1024];      // packed bbk|bbq
__device__ float g_BPP[1024];      // packed bpk|bpq

// offsets into g_WT (floats)
#define WT_QK   0          // 512x1024
#define WT_BKBQ 524288     // 512x1024
#define WT_PKPQ 1048576    // 512x1024
#define WT_V    1572864    // 512x512
#define WT_D    1835008    // 512x512
#define WT_1    2097152    // 512x2048
#define WT_2    3145728    // 2048x512

// ---------------- helpers ----------------
__device__ __forceinline__ uint32_t smem_u32(const void* p) {
    uint32_t a;
    asm("{ .reg .u64 t; cvta.to.shared.u64 t, %1; cvt.u32.u64 %0, t; }"
        : "=r"(a) : "l"(p));
    return a;
}

__device__ __forceinline__ float to_tf32(float x) {
    float r;
    asm("cvt.rna.tf32.f32 %0, %1;" : "=f"(r) : "f"(x));
    return r;
}

__device__ __forceinline__ void mma8(float* c, const uint32_t* a, uint32_t b0, uint32_t b1) {
    asm volatile(
        "mma.sync.aligned.m16n8k8.row.col.f32.tf32.tf32.f32 "
        "{%0,%1,%2,%3}, {%4,%5,%6,%7}, {%8,%9}, {%0,%1,%2,%3};"
        : "+f"(c[0]), "+f"(c[1]), "+f"(c[2]), "+f"(c[3])
        : "r"(a[0]), "r"(a[1]), "r"(a[2]), "r"(a[3]), "r"(b0), "r"(b1));
}

__device__ __forceinline__ void cpa16(uint32_t saddr, const void* gaddr) {
    asm volatile("cp.async.cg.shared.global [%0], [%1], 16;" :: "r"(saddr), "l"(gaddr));
}
#define CP_COMMIT() asm volatile("cp.async.commit_group;" ::: "memory")
#define CP_WAIT(n)  asm volatile("cp.async.wait_group %0;" :: "n"(n) : "memory")

// ================= unified prep kernel (weights only) =================
__device__ __forceinline__ float4 rnd4(float4 v) {
    v.x = to_tf32(v.x); v.y = to_tf32(v.y);
    v.z = to_tf32(v.z); v.w = to_tf32(v.w);
    return v;
}

// flat f4 ranges
#define PR_WV   0
#define PR_WD   65536
#define PR_W1   131072
#define PR_W2   393216
#define PR_QK   655360
#define PR_BKBQ 786432
#define PR_PKPQ 917504
#define PR_END  1048576

__global__ void prep_kernel(const float* __restrict__ Wv, const float* __restrict__ Wd,
                            const float* __restrict__ W1, const float* __restrict__ W2,
                            const float* __restrict__ Wq,  const float* __restrict__ Wk,
                            const float* __restrict__ Wbk, const float* __restrict__ Wbq,
                            const float* __restrict__ Wpk, const float* __restrict__ Wpq,
                            const float* __restrict__ bq,  const float* __restrict__ bk,
                            const float* __restrict__ bbk, const float* __restrict__ bbq,
                            const float* __restrict__ bpk, const float* __restrict__ bpq)
{
    int i = blockIdx.x * blockDim.x + threadIdx.x;
    if (i >= PR_END) return;

    if (i < PR_QK) {
        const float* p; float* q; int off;
        if (i < PR_WD)       { p = Wv;   q = g_WT + WT_V;    off = i; }
        else if (i < PR_W1)  { p = Wd;   q = g_WT + WT_D;    off = i - PR_WD; }
        else if (i < PR_W2)  { p = W1;   q = g_WT + WT_1;    off = i - PR_W1; }
        else                 { p = W2;   q = g_WT + WT_2;    off = i - PR_W2; }
        ((float4*)q)[off] = rnd4(((const float4*)p)[off]);
    } else {
        const float *A1, *A2, *c1, *c2; float *outW, *outB; int local;
        if (i < PR_BKBQ)      { A1 = Wq;  A2 = Wk;  c1 = bq;  c2 = bk;  outW = g_WT + WT_QK;   outB = g_BQK; local = i - PR_QK; }
        else if (i < PR_PKPQ) { A1 = Wbk; A2 = Wbq; c1 = bbk; c2 = bbq; outW = g_WT + WT_BKBQ; outB = g_BB2; local = i - PR_BKBQ; }
        else                  { A1 = Wpk; A2 = Wpq; c1 = bpk; c2 = bpq; outW = g_WT + WT_PKPQ; outB = g_BPP; local = i - PR_PKPQ; }
        int row = local >> 8;
        int c4 = local & 255;
        const float* src = (c4 < 128) ? (A1 + (size_t)row * 512 + c4 * 4)
                                      : (A2 + (size_t)row * 512 + (c4 - 128) * 4);
        ((float4*)outW)[local] = rnd4(*(const float4*)src);
        if (local < 256) {
            int c = local * 4;
            const float* sb = (c < 512) ? (c1 + c) : (c2 + c - 512);
            *(float4*)(outB + c) = *(const float4*)sb;
        }
    }
}

// ================= GEMM core pieces =================
#define STG_FLOATS 8960                 // A 128*36 + B 32*136
#define GEMM_SMEM (3*STG_FLOATS*4)      // 107520 bytes

__device__ __forceinline__ void gemm_issue(uint32_t sstage,
                                           const float* __restrict__ A,
                                           const float* __restrict__ W,
                                           int m0, int n0, int K, int N, int c, int tid)
{
    const float* Ag = A + (size_t)m0 * K + c * 32;
    const float* Wg = W + (size_t)(c * 32) * N + n0;
    #pragma unroll
    for (int i = 0; i < 4; i++) {
        int f = tid + i * 256;
        int r = f >> 3, kq = (f & 7) * 4;
        cpa16(sstage + (uint32_t)(r * 36 + kq) * 4, Ag + (size_t)r * K + kq);
    }
    #pragma unroll
    for (int i = 0; i < 4; i++) {
        int f = tid + i * 256;
        int kr = f >> 5, nq = (f & 31) * 4;
        cpa16(sstage + (uint32_t)(4608 + kr * 136 + nq) * 4, Wg + (size_t)kr * N + nq);
    }
}

// shared mainloop: accumulates 32x64-per-warp tile over K
__device__ __forceinline__ void gemm_mainloop(float* sm, uint32_t sbase,
                                              const float* __restrict__ A,
                                              const float* __restrict__ W,
                                              int m0, int n0, int K, int N,
                                              int tid, int wm, int wn, int g, int tg,
                                              float acc[2][8][4])
{
    const int NC = K >> 5;
    gemm_issue(sbase,                  A, W, m0, n0, K, N, 0, tid); CP_COMMIT();
    gemm_issue(sbase + STG_FLOATS * 4, A, W, m0, n0, K, N, 1, tid); CP_COMMIT();

    for (int c = 0; c < NC; c++) {
        CP_WAIT(1);
        __syncthreads();
        if (c + 2 < NC)
            gemm_issue(sbase + (uint32_t)((c + 2) % 3) * (STG_FLOATS * 4),
                       A, W, m0, n0, K, N, c + 2, tid);
        CP_COMMIT();

        float (*As)[36]  = (float(*)[36]) (sm + (c % 3) * STG_FLOATS);
        float (*Bs)[136] = (float(*)[136])(sm + (c % 3) * STG_FLOATS + 4608);
        #pragma unroll
        for (int ks = 0; ks < 4; ks++) {
            int k0 = ks * 8;
            uint32_t a[2][4];
            #pragma unroll
            for (int mi = 0; mi < 2; mi++) {
                int row = wm + mi * 16 + g;
                a[mi][0] = __float_as_uint(As[row    ][k0 + tg]);
                a[mi][1] = __float_as_uint(As[row + 8][k0 + tg]);
                a[mi][2] = __float_as_uint(As[row    ][k0 + tg + 4]);
                a[mi][3] = __float_as_uint(As[row + 8][k0 + tg + 4]);
            }
            #pragma unroll
            for (int nj = 0; nj < 8; nj++) {
                int col = wn + nj * 8 + g;
                uint32_t b0 = __float_as_uint(Bs[k0 + tg    ][col]);
                uint32_t b1 = __float_as_uint(Bs[k0 + tg + 4][col]);
                mma8(acc[0][nj], a[0], b0, b1);
                mma8(acc[1][nj], a[1], b0, b1);
            }
        }
    }
}

// ================= generic mma GEMM (for pos, D, FFN) ======================
// EPI: 0 bias, 1 +residual, 2 gelu, 3 split write (C/C2 512-halves)
template<int EPI, int TF32OUT>
__global__ void __launch_bounds__(256, 2)
mma_gemm(const float* __restrict__ A, const float* __restrict__ W,
         const float* __restrict__ bias, const float* __restrict__ Rres,
         float* __restrict__ C, float* __restrict__ C2,
         int M, int N, int K)
{
    extern __shared__ __align__(16) float sm[];
    const uint32_t sbase = smem_u32(sm);
    const int tid  = threadIdx.x;
    const int lane = tid & 31;
    const int wid  = tid >> 5;
    const int wm   = (wid & 3) * 32;
    const int wn   = (wid >> 2) * 64;
    const int m0 = blockIdx.y * 128;
    const int n0 = blockIdx.x * 128;
    const int g  = lane >> 2;
    const int tg = lane & 3;

    float acc[2][8][4];
    #pragma unroll
    for (int i = 0; i < 2; i++)
        #pragma unroll
        for (int j = 0; j < 8; j++)
            #pragma unroll
            for (int q = 0; q < 4; q++) acc[i][j][q] = 0.0f;

    gemm_mainloop(sm, sbase, A, W, m0, n0, K, N, tid, wm, wn, g, tg, acc);

    #pragma unroll
    for (int mi = 0; mi < 2; mi++) {
        #pragma unroll
        for (int nj = 0; nj < 8; nj++) {
            int r0  = m0 + wm + mi * 16 + g;
            int colG = n0 + wn + nj * 8 + 2 * tg;
            float b0 = bias[colG], b1 = bias[colG + 1];
            float v00 = acc[mi][nj][0] + b0, v01 = acc[mi][nj][1] + b1;
            float v10 = acc[mi][nj][2] + b0, v11 = acc[mi][nj][3] + b1;

            if (EPI == 1) {
                v00 += Rres[(size_t)r0 * N + colG];
                v01 += Rres[(size_t)r0 * N + colG + 1];
                v10 += Rres[(size_t)(r0 + 8) * N + colG];
                v11 += Rres[(size_t)(r0 + 8) * N + colG + 1];
            }
            if (EPI == 2) {
                v00 = 0.5f * v00 * (1.0f + erff(v00 * 0.7071067811865475f));
                v01 = 0.5f * v01 * (1.0f + erff(v01 * 0.7071067811865475f));
                v10 = 0.5f * v10 * (1.0f + erff(v10 * 0.7071067811865475f));
                v11 = 0.5f * v11 * (1.0f + erff(v11 * 0.7071067811865475f));
            }
            if (TF32OUT) {
                v00 = to_tf32(v00); v01 = to_tf32(v01);
                v10 = to_tf32(v10); v11 = to_tf32(v11);
            }
            if (EPI == 3) {
                const bool half = colG >= 512;
                const int coln = colG - (half ? 512 : 0);
                float* Cw = half ? C2 : C;
                *(float2*)(Cw + (size_t)r0 * 512 + coln)       = make_float2(v00, v01);
                *(float2*)(Cw + (size_t)(r0 + 8) * 512 + coln) = make_float2(v10, v11);
            } else {
                *(float2*)(C + (size_t)r0 * N + colG)       = make_float2(v00, v01);
                *(float2*)(C + (size_t)(r0 + 8) * N + colG) = make_float2(v10, v11);
            }
        }
    }
}

// ================= uber projection kernel: QK | BKBQ | V in one launch =====
// 2560 CTAs: [0,1024) QK, [1024,2048) BKBQ, [2048,2560) V
__global__ void __launch_bounds__(256, 2)
proj_uber(const float* __restrict__ x, const float* __restrict__ beha,
          const float* __restrict__ vin, const float* __restrict__ bv)
{
    extern __shared__ __align__(16) float sm[];
    const uint32_t sbase = smem_u32(sm);
    const int tid  = threadIdx.x;
    const int lane = tid & 31;
    const int wid  = tid >> 5;
    const int wm   = (wid & 3) * 32;
    const int wn   = (wid >> 2) * 64;
    const int g  = lane >> 2;
    const int tg = lane & 3;

    const int bid = blockIdx.x;
    int seg, m0, n0, N;
    const float *A, *W, *bias;
    if (bid < 1024) {
        seg = 0; A = x; W = g_WT + WT_QK; bias = g_BQK; N = 1024;
        n0 = (bid & 7) * 128; m0 = (bid >> 3) * 128;
    } else if (bid < 2048) {
        seg = 1; A = beha; W = g_WT + WT_BKBQ; bias = g_BB2; N = 1024;
        int l = bid - 1024;
        n0 = (l & 7) * 128; m0 = (l >> 3) * 128;
    } else {
        seg = 2; A = vin; W = g_WT + WT_V; bias = bv; N = 512;
        int l = bid - 2048;
        n0 = (l & 3) * 128; m0 = (l >> 2) * 128;
    }

    float acc[2][8][4];
    #pragma unroll
    for (int i = 0; i < 2; i++)
        #pragma unroll
        for (int j = 0; j < 8; j++)
            #pragma unroll
            for (int q = 0; q < 4; q++) acc[i][j][q] = 0.0f;

    gemm_mainloop(sm, sbase, A, W, m0, n0, 512, N, tid, wm, wn, g, tg, acc);

    #pragma unroll
    for (int mi = 0; mi < 2; mi++) {
        #pragma unroll
        for (int nj = 0; nj < 8; nj++) {
            int r0  = m0 + wm + mi * 16 + g;
            int colG = n0 + wn + nj * 8 + 2 * tg;
            float b0 = bias[colG], b1 = bias[colG + 1];
            float v00 = acc[mi][nj][0] + b0, v01 = acc[mi][nj][1] + b1;
            float v10 = acc[mi][nj][2] + b0, v11 = acc[mi][nj][3] + b1;

            if (seg == 2) {
                // V projection + residual, write g_V (N=512)
                v00 += vin[(size_t)r0 * 512 + colG];
                v01 += vin[(size_t)r0 * 512 + colG + 1];
                v10 += vin[(size_t)(r0 + 8) * 512 + colG];
                v11 += vin[(size_t)(r0 + 8) * 512 + colG + 1];
                *(float2*)(g_V + (size_t)r0 * 512 + colG) =
                    make_float2(to_tf32(v00), to_tf32(v01));
                *(float2*)(g_V + (size_t)(r0 + 8) * 512 + colG) =
                    make_float2(to_tf32(v10), to_tf32(v11));
            } else {
                const bool half = colG >= 512;
                const int coln = colG - (half ? 512 : 0);
                float* Cw;
                if (seg == 0) {
                    Cw = half ? g_K : g_Q;
                } else {
                    // BKBQ: 0.5*(acc+bias+P)
                    int s0 = r0 & (S - 1);
                    const float* P = half ? g_PQ : g_PK;
                    v00 = 0.5f * (v00 + P[(size_t)s0 * 512 + coln]);
                    v01 = 0.5f * (v01 + P[(size_t)s0 * 512 + coln + 1]);
                    v10 = 0.5f * (v10 + P[(size_t)(s0 + 8) * 512 + coln]);
                    v11 = 0.5f * (v11 + P[(size_t)(s0 + 8) * 512 + coln + 1]);
                    Cw = half ? g_QH : g_HK;
                }
                *(float2*)(Cw + (size_t)r0 * 512 + coln) =
                    make_float2(to_tf32(v00), to_tf32(v01));
                *(float2*)(Cw + (size_t)(r0 + 8) * 512 + coln) =
                    make_float2(to_tf32(v10), to_tf32(v11));
            }
        }
    }
}

// ================= fused flash attention =================
// scores = (Q+QH)·K^T + Q·HK^T
#define FL_STAGE 13376   // Kt 64*68 + HKt 64*68 + Vs 64*72 + 64 mask
#define FL_PS_OFF (2*FL_STAGE)
#define FL_SMEM ((2*FL_STAGE + 128*68) * 4)   // 141824 bytes

__device__ __forceinline__ void flash_issue(uint32_t st, int b, int h, int k0,
                                            int tid, const int* __restrict__ iseq)
{
    const float* Kg  = g_K  + ((size_t)(b * S + k0)) * H + h * DH;
    const float* HKg = g_HK + ((size_t)(b * S + k0)) * H + h * DH;
    const float* Vg  = g_V  + ((size_t)(b * S + k0)) * H + h * DH;
    #pragma unroll
    for (int i = 0; i < 4; i++) {
        int f = tid + i * 256;
        int r = f >> 4, cq = (f & 15) * 4;
        size_t go = (size_t)r * H + cq;
        cpa16(st + (uint32_t)(r * 68 + cq) * 4,          Kg  + go);
        cpa16(st + (uint32_t)(4352 + r * 68 + cq) * 4,   HKg + go);
        cpa16(st + (uint32_t)(8704 + r * 72 + cq) * 4,   Vg  + go);
    }
    if (tid < 16)
        cpa16(st + (13312 + tid * 4) * 4, iseq + b * S + k0 + tid * 4);
}

__global__ void __launch_bounds__(256)
flash_attn(const int* __restrict__ iseq)
{
    extern __shared__ __align__(16) float sm[];
    const uint32_t sbase = smem_u32(sm);

    const int bz = blockIdx.y;
    const int b = bz >> 3;
    const int h = bz & 7;
    const int qt = 3 - blockIdx.x;
    const int q0 = qt * 128;
    const int tid = threadIdx.x;
    const int lane = tid & 31;
    const int wid = tid >> 5;
    const int r0 = wid * 16;
    const int g = lane >> 2;
    const int tg = lane & 3;

    const int n_kt = 2 * qt + 2;

    uint32_t qs[8][4], qo[8][4];
    {
        const float* Qp  = g_Q  + ((size_t)(b * S + q0 + r0 + g)) * H + h * DH;
        const float* Qp8 = Qp + 8 * H;
        const float* Hp  = g_QH + ((size_t)(b * S + q0 + r0 + g)) * H + h * DH;
        const float* Hp8 = Hp + 8 * H;
        #pragma unroll
        for (int ks = 0; ks < 8; ks++) {
            int c = ks * 8 + tg;
            float q00 = __ldg(Qp  + c),     q10 = __ldg(Qp8 + c);
            float q01 = __ldg(Qp  + c + 4), q11 = __ldg(Qp8 + c + 4);
            float h00 = __ldg(Hp  + c),     h10 = __ldg(Hp8 + c);
            float h01 = __ldg(Hp  + c + 4), h11 = __ldg(Hp8 + c + 4);
            qo[ks][0] = __float_as_uint(q00);
            qo[ks][1] = __float_as_uint(q10);
            qo[ks][2] = __float_as_uint(q01);
            qo[ks][3] = __float_as_uint(q11);
            qs[ks][0] = __float_as_uint(to_tf32(q00 + h00));
            qs[ks][1] = __float_as_uint(to_tf32(q10 + h10));
            qs[ks][2] = __float_as_uint(to_tf32(q01 + h01));
            qs[ks][3] = __float_as_uint(to_tf32(q11 + h11));
        }
    }

    float oacc[8][4];
    #pragma unroll
    for (int i = 0; i < 8; i++)
        #pragma unroll
        for (int q = 0; q < 4; q++) oacc[i][q] = 0.0f;
    float mrow[2] = {-1e30f, -1e30f};
    float lrow[2] = {0.0f, 0.0f};

    flash_issue(sbase, b, h, 0, tid, iseq); CP_COMMIT();

    for (int j = 0; j < n_kt; j++) {
        const int k0 = j * 64;
        const bool causal = (j >= 2 * qt);
        const int stg = j & 1;

        CP_WAIT(0);
        __syncthreads();
        if (j + 1 < n_kt)
            flash_issue(sbase + (uint32_t)((j + 1) & 1) * (FL_STAGE * 4),
                        b, h, (j + 1) * 64, tid, iseq);
        CP_COMMIT();

        float (*Kt )[68] = (float(*)[68])(sm + stg * FL_STAGE);
        float (*HKt)[68] = (float(*)[68])(sm + stg * FL_STAGE + 4352);
        float (*Vs )[72] = (float(*)[72])(sm + stg * FL_STAGE + 8704);
        const int* maskv = (const int*)(sm + stg * FL_STAGE + 13312);

        float sacc[8][4];
        #pragma unroll
        for (int i = 0; i < 8; i++)
            #pragma unroll
            for (int q = 0; q < 4; q++) sacc[i][q] = 0.0f;

        #pragma unroll
        for (int ks = 0; ks < 8; ks++) {
            int kk = ks * 8;
            #pragma unroll
            for (int nj = 0; nj < 8; nj++) {
                int col = nj * 8 + g;
                uint32_t bk0  = __float_as_uint(Kt [col][kk + tg]);
                uint32_t bk1  = __float_as_uint(Kt [col][kk + tg + 4]);
                uint32_t bh0  = __float_as_uint(HKt[col][kk + tg]);
                uint32_t bh1  = __float_as_uint(HKt[col][kk + tg + 4]);
                mma8(sacc[nj], qs[ks], bk0, bk1);
                mma8(sacc[nj], qo[ks], bh0, bh1);
            }
        }

        float (*Ps)[68] = (float(*)[68])(sm + FL_PS_OFF);
        #pragma unroll
        for (int h2 = 0; h2 < 2; h2++) {
            int grow = q0 + r0 + g + 8 * h2;
            float sv[16];
            float tmax = -1e30f;
            #pragma unroll
            for (int nj = 0; nj < 8; nj++) {
                #pragma unroll
                for (int cc = 0; cc < 2; cc++) {
                    int c = nj * 8 + 2 * tg + cc;
                    float madd = (!causal || (k0 + c <= grow))
                                 ? ((maskv[c] > 0) ? 0.0f : -10000.0f)
                                 : -10000.0f;
                    float s = sacc[nj][h2 * 2 + cc] * 0.125f + madd;
                    sv[nj * 2 + cc] = s;
                    tmax = fmaxf(tmax, s);
                }
            }
            tmax = fmaxf(tmax, __shfl_xor_sync(0xffffffffu, tmax, 1));
            tmax = fmaxf(tmax, __shfl_xor_sync(0xffffffffu, tmax, 2));
            float mnew = fmaxf(mrow[h2], tmax);
            float scale = __expf(mrow[h2] - mnew);
            mrow[h2] = mnew;
            float rs = 0.0f;
            #pragma unroll
            for (int nj = 0; nj < 8; nj++) {
                float p0 = __expf(sv[nj * 2]     - mnew);
                float p1 = __expf(sv[nj * 2 + 1] - mnew);
                rs += p0 + p1;
                *(float2*)&Ps[r0 + g + 8 * h2][nj * 8 + 2 * tg] =
                    make_float2(to_tf32(p0), to_tf32(p1));
            }
            rs += __shfl_xor_sync(0xffffffffu, rs, 1);
            rs += __shfl_xor_sync(0xffffffffu, rs, 2);
            lrow[h2] = lrow[h2] * scale + rs;
            #pragma unroll
            for (int nd = 0; nd < 8; nd++) {
                oacc[nd][h2 * 2]     *= scale;
                oacc[nd][h2 * 2 + 1] *= scale;
            }
        }
        __syncwarp();

        #pragma unroll
        for (int ks = 0; ks < 8; ks++) {
            int kk = ks * 8;
            uint32_t pa[4];
            pa[0] = __float_as_uint(Ps[r0 + g    ][kk + tg]);
            pa[1] = __float_as_uint(Ps[r0 + g + 8][kk + tg]);
            pa[2] = __float_as_uint(Ps[r0 + g    ][kk + tg + 4]);
            pa[3] = __float_as_uint(Ps[r0 + g + 8][kk + tg + 4]);
            #pragma unroll
            for (int nd = 0; nd < 8; nd++) {
                int col = nd * 8 + g;
                uint32_t b0 = __float_as_uint(Vs[kk + tg    ][col]);
                uint32_t b1 = __float_as_uint(Vs[kk + tg + 4][col]);
                mma8(oacc[nd], pa, b0, b1);
            }
        }
    }

    float inv0 = 1.0f / lrow[0];
    float inv1 = 1.0f / lrow[1];
    size_t base = ((size_t)(b * S + q0 + r0 + g)) * H + h * DH;
    #pragma unroll
    for (int nd = 0; nd < 8; nd++) {
        int c = nd * 8 + 2 * tg;
        *(float2*)(g_CTX + base + c) =
            make_float2(to_tf32(oacc[nd][0] * inv0), to_tf32(oacc[nd][1] * inv0));
        *(float2*)(g_CTX + base + 8 * H + c) =
            make_float2(to_tf32(oacc[nd][2] * inv1), to_tf32(oacc[nd][3] * inv1));
    }
}

// ---------------- LayerNorm -----------------
template<int ROUND>
__global__ __launch_bounds__(256)
void ln_kernel(const float* __restrict__ in, const float* __restrict__ gam,
               const float* __restrict__ bet, float* __restrict__ out)
{
    size_t row = blockIdx.x;
    const float* p = in + row * H;
    int t = threadIdx.x;
    float x0 = p[t], x1 = p[t + 256];

    __shared__ float r1[8], r2[8];
    float s = x0 + x1;
    float sq = x0 * x0 + x1 * x1;
    #pragma unroll
    for (int o = 16; o; o >>= 1) {
        s  += __shfl_xor_sync(0xffffffffu, s, o);
        sq += __shfl_xor_sync(0xffffffffu, sq, o);
    }
    if ((t & 31) == 0) { r1[t >> 5] = s; r2[t >> 5] = sq; }
    __syncthreads();
    if (t == 0) {
        float S1 = 0.0f, S2 = 0.0f;
        #pragma unroll
        for (int i = 0; i < 8; i++) { S1 += r1[i]; S2 += r2[i]; }
        r1[0] = S1; r2[0] = S2;
    }
    __syncthreads();
    float mean = r1[0] * (1.0f / (float)H);
    float var  = r2[0] * (1.0f / (float)H) - mean * mean;
    float rstd = rsqrtf(var + 1e-12f);
    float o0 = (x0 - mean) * rstd * gam[t]       + bet[t];
    float o1 = (x1 - mean) * rstd * gam[t + 256] + bet[t + 256];
    if (ROUND) { o0 = to_tf32(o0); o1 = to_tf32(o1); }
    out[row * H + t]       = o0;
    out[row * H + t + 256] = o1;
}

// ---------------- launcher ----------------
extern "C" void kernel_launch(void* const* d_in, const int* in_sizes, int n_in,
                              void* d_out, int out_size)
{
    const float* x    = (const float*)d_in[0];
    const float* vin  = (const float*)d_in[1];
    const float* beha = (const float*)d_in[2];
    const float* pos  = (const float*)d_in[3];
    const float* Wq   = (const float*)d_in[4];
    const float* bq   = (const float*)d_in[5];
    const float* Wk   = (const float*)d_in[6];
    const float* bk   = (const float*)d_in[7];
    const float* Wv   = (const float*)d_in[8];
    const float* bv   = (const float*)d_in[9];
    const float* Wpk  = (const float*)d_in[10];
    const float* bpk  = (const float*)d_in[11];
    const float* Wpq  = (const float*)d_in[12];
    const float* bpq  = (const float*)d_in[13];
    const float* Wbk  = (const float*)d_in[14];
    const float* bbk  = (const float*)d_in[15];
    const float* Wbq  = (const float*)d_in[16];
    const float* bbq  = (const float*)d_in[17];
    const float* Wd   = (const float*)d_in[18];
    const float* bd   = (const float*)d_in[19];
    const float* ln_g = (const float*)d_in[20];
    const float* ln_b = (const float*)d_in[21];
    const float* W1   = (const float*)d_in[22];
    const float* b1   = (const float*)d_in[23];
    const float* W2   = (const float*)d_in[24];
    const float* b2   = (const float*)d_in[25];
    const float* ln2g = (const float*)d_in[26];
    const float* ln2b = (const float*)d_in[27];
    const int*   iseq = (const int*)d_in[28];
    float* out = (float*)d_out;

    float *pQ, *pK, *pV, *pHK, *pQH, *pPK, *pPQ, *pCTX, *pATT, *pAO, *pH1, *pWT;
    float *pBQK, *pBB2, *pBPP;
    cudaGetSymbolAddress((void**)&pQ,   g_Q);
    cudaGetSymbolAddress((void**)&pK,   g_K);
    cudaGetSymbolAddress((void**)&pV,   g_V);
    cudaGetSymbolAddress((void**)&pHK,  g_HK);
    cudaGetSymbolAddress((void**)&pQH,  g_QH);
    cudaGetSymbolAddress((void**)&pPK,  g_PK);
    cudaGetSymbolAddress((void**)&pPQ,  g_PQ);
    cudaGetSymbolAddress((void**)&pCTX, g_CTX);
    cudaGetSymbolAddress((void**)&pATT, g_ATT);
    cudaGetSymbolAddress((void**)&pAO,  g_AO);
    cudaGetSymbolAddress((void**)&pH1,  g_H1);
    cudaGetSymbolAddress((void**)&pWT,  g_WT);
    cudaGetSymbolAddress((void**)&pBQK, g_BQK);
    cudaGetSymbolAddress((void**)&pBB2, g_BB2);
    cudaGetSymbolAddress((void**)&pBPP, g_BPP);

    cudaFuncSetAttribute(mma_gemm<1,0>, cudaFuncAttributeMaxDynamicSharedMemorySize, GEMM_SMEM);
    cudaFuncSetAttribute(mma_gemm<2,1>, cudaFuncAttributeMaxDynamicSharedMemorySize, GEMM_SMEM);
    cudaFuncSetAttribute(mma_gemm<3,0>, cudaFuncAttributeMaxDynamicSharedMemorySize, GEMM_SMEM);
    cudaFuncSetAttribute(proj_uber,  cudaFuncAttributeMaxDynamicSharedMemorySize, GEMM_SMEM);
    cudaFuncSetAttribute(flash_attn, cudaFuncAttributeMaxDynamicSharedMemorySize, FL_SMEM);

    dim3 blk(256);

    // ---- prep (weights + biases) ----
    prep_kernel<<<(PR_END + 255) / 256, blk>>>(Wv, Wd, W1, W2,
                                               Wq, Wk, Wbk, Wbq, Wpk, Wpq,
                                               bq, bk, bbk, bbq, bpk, bpq);

    // pos PK|PQ projection (needed by uber's BKBQ epilogue)
    dim3 gPos(1024 / 128, S / 128);
    mma_gemm<3,0><<<gPos, blk, GEMM_SMEM>>>(pos, pWT + WT_PKPQ, pBPP, nullptr, pPK, pPQ, S, 1024, H);

    // fused QK | BKBQ | V projections in one dense launch
    proj_uber<<<2560, blk, GEMM_SMEM>>>(x, beha, vin, bv);

    // fused attention
    flash_attn<<<dim3(S / 128, B * NH), blk, FL_SMEM>>>(iseq);

    dim3 gProj(512 / 128, BS / 128);
    mma_gemm<1,0><<<gProj, blk, GEMM_SMEM>>>(pCTX, pWT + WT_D, bd, x, pATT, nullptr, BS, H, H);
    ln_kernel<1><<<BS, blk>>>(pATT, ln_g, ln_b, pAO);

    dim3 gF1(INNER / 128, BS / 128);
    mma_gemm<2,1><<<gF1, blk, GEMM_SMEM>>>(pAO, pWT + WT_1, b1, nullptr, pH1, nullptr, BS, INNER, H);
    mma_gemm<1,0><<<gProj, blk, GEMM_SMEM>>>(pH1, pWT + WT_2, b2, pAO, pATT, nullptr, BS, H, INNER);
    ln_kernel<0><<<BS, blk>>>(pATT, ln2g, ln2b, out);
}

// round 13
// speedup vs baseline: 1.0142x; 1.0142x over previous
#include <cuda_runtime.h>
#include <math.h>
#include <stdint.h>

// ---------------- problem constants ----------------
#define B 32
#define S 512
#define H 512
#define NH 8
#define DH 64
#define INNER 2048
#define BS (B*S)            // 16384
#define BSH ((size_t)B*S*H) // 8388608

// ---------------- scratch ----------------
__device__ float g_Q  [BSH];
__device__ float g_K  [BSH];
__device__ float g_V  [BSH];
__device__ float g_HK [BSH];   // 0.5*(bhk + pk)
__device__ float g_QH [BSH];   // 0.5*(bhq + pq)
__device__ float g_PK [S*H];
__device__ float g_PQ [S*H];
__device__ float g_CTX[BSH];
__device__ float g_ATT[BSH];
__device__ float g_AO [BSH];
__device__ float g_H1 [(size_t)BS*INNER];
__device__ float g_WT [4194304];   // tf32 weights pool
__device__ float g_BQK[1024];      // packed bq|bk
__device__ float g_BB2[1024];      // packed bbk|bbq
__device__ float g_BPP[1024];      // packed bpk|bpq

// offsets into g_WT (floats)
#define WT_QK   0          // 512x1024
#define WT_BKBQ 524288     // 512x1024
#define WT_PKPQ 1048576    // 512x1024
#define WT_V    1572864    // 512x512
#define WT_D    1835008    // 512x512
#define WT_1    2097152    // 512x2048
#define WT_2    3145728    // 2048x512

// ---------------- helpers ----------------
__device__ __forceinline__ uint32_t smem_u32(const void* p) {
    uint32_t a;
    asm("{ .reg .u64 t; cvta.to.shared.u64 t, %1; cvt.u32.u64 %0, t; }"
        : "=r"(a) : "l"(p));
    return a;
}

__device__ __forceinline__ float to_tf32(float x) {
    float r;
    asm("cvt.rna.tf32.f32 %0, %1;" : "=f"(r) : "f"(x));
    return r;
}

__device__ __forceinline__ void mma8(float* c, const uint32_t* a, uint32_t b0, uint32_t b1) {
    asm volatile(
        "mma.sync.aligned.m16n8k8.row.col.f32.tf32.tf32.f32 "
        "{%0,%1,%2,%3}, {%4,%5,%6,%7}, {%8,%9}, {%0,%1,%2,%3};"
        : "+f"(c[0]), "+f"(c[1]), "+f"(c[2]), "+f"(c[3])
        : "r"(a[0]), "r"(a[1]), "r"(a[2]), "r"(a[3]), "r"(b0), "r"(b1));
}

__device__ __forceinline__ void cpa16(uint32_t saddr, const void* gaddr) {
    asm volatile("cp.async.cg.shared.global [%0], [%1], 16;" :: "r"(saddr), "l"(gaddr));
}
#define CP_COMMIT() asm volatile("cp.async.commit_group;" ::: "memory")
#define CP_WAIT(n)  asm volatile("cp.async.wait_group %0;" :: "n"(n) : "memory")

// ================= unified prep kernel (weights only) =================
__device__ __forceinline__ float4 rnd4(float4 v) {
    v.x = to_tf32(v.x); v.y = to_tf32(v.y);
    v.z = to_tf32(v.z); v.w = to_tf32(v.w);
    return v;
}

// flat f4 ranges
#define PR_WV   0
#define PR_WD   65536
#define PR_W1   131072
#define PR_W2   393216
#define PR_QK   655360
#define PR_BKBQ 786432
#define PR_PKPQ 917504
#define PR_END  1048576

__global__ void prep_kernel(const float* __restrict__ Wv, const float* __restrict__ Wd,
                            const float* __restrict__ W1, const float* __restrict__ W2,
                            const float* __restrict__ Wq,  const float* __restrict__ Wk,
                            const float* __restrict__ Wbk, const float* __restrict__ Wbq,
                            const float* __restrict__ Wpk, const float* __restrict__ Wpq,
                            const float* __restrict__ bq,  const float* __restrict__ bk,
                            const float* __restrict__ bbk, const float* __restrict__ bbq,
                            const float* __restrict__ bpk, const float* __restrict__ bpq)
{
    int i = blockIdx.x * blockDim.x + threadIdx.x;
    if (i >= PR_END) return;

    if (i < PR_QK) {
        const float* p; float* q; int off;
        if (i < PR_WD)       { p = Wv;   q = g_WT + WT_V;    off = i; }
        else if (i < PR_W1)  { p = Wd;   q = g_WT + WT_D;    off = i - PR_WD; }
        else if (i < PR_W2)  { p = W1;   q = g_WT + WT_1;    off = i - PR_W1; }
        else                 { p = W2;   q = g_WT + WT_2;    off = i - PR_W2; }
        ((float4*)q)[off] = rnd4(((const float4*)p)[off]);
    } else {
        const float *A1, *A2, *c1, *c2; float *outW, *outB; int local;
        if (i < PR_BKBQ)      { A1 = Wq;  A2 = Wk;  c1 = bq;  c2 = bk;  outW = g_WT + WT_QK;   outB = g_BQK; local = i - PR_QK; }
        else if (i < PR_PKPQ) { A1 = Wbk; A2 = Wbq; c1 = bbk; c2 = bbq; outW = g_WT + WT_BKBQ; outB = g_BB2; local = i - PR_BKBQ; }
        else                  { A1 = Wpk; A2 = Wpq; c1 = bpk; c2 = bpq; outW = g_WT + WT_PKPQ; outB = g_BPP; local = i - PR_PKPQ; }
        int row = local >> 8;
        int c4 = local & 255;
        const float* src = (c4 < 128) ? (A1 + (size_t)row * 512 + c4 * 4)
                                      : (A2 + (size_t)row * 512 + (c4 - 128) * 4);
        ((float4*)outW)[local] = rnd4(*(const float4*)src);
        if (local < 256) {
            int c = local * 4;
            const float* sb = (c < 512) ? (c1 + c) : (c2 + c - 512);
            *(float4*)(outB + c) = *(const float4*)sb;
        }
    }
}

// ================= mma.sync tf32 GEMM, 128x128 tile, cp.async 3-stage ======
// EPI: 0 bias, 1 +residual, 2 gelu, 3 split write (C/C2 512-halves),
//      5 split combine: both halves = 0.5*(acc+bias+Psel)
#define STG_FLOATS 8960                 // A 128*36 + B 32*136
#define GEMM_SMEM (3*STG_FLOATS*4)      // 107520 bytes

__device__ __forceinline__ void gemm_issue(uint32_t sstage,
                                           const float* __restrict__ A,
                                           const float* __restrict__ W,
                                           int m0, int n0, int K, int N, int c, int tid)
{
    const float* Ag = A + (size_t)m0 * K + c * 32;
    const float* Wg = W + (size_t)(c * 32) * N + n0;
    #pragma unroll
    for (int i = 0; i < 4; i++) {
        int f = tid + i * 256;
        int r = f >> 3, kq = (f & 7) * 4;
        cpa16(sstage + (uint32_t)(r * 36 + kq) * 4, Ag + (size_t)r * K + kq);
    }
    #pragma unroll
    for (int i = 0; i < 4; i++) {
        int f = tid + i * 256;
        int kr = f >> 5, nq = (f & 31) * 4;
        cpa16(sstage + (uint32_t)(4608 + kr * 136 + nq) * 4, Wg + (size_t)kr * N + nq);
    }
}

template<int EPI, int TF32OUT>
__global__ void __launch_bounds__(256, 2)
mma_gemm(const float* __restrict__ A, const float* __restrict__ W,
         const float* __restrict__ bias, const float* __restrict__ Rres,
         const float* __restrict__ P1, const float* __restrict__ P2,
         float* __restrict__ C, float* __restrict__ C2,
         int M, int N, int K)
{
    extern __shared__ __align__(16) float sm[];
    const uint32_t sbase = smem_u32(sm);
    const int tid  = threadIdx.x;
    const int lane = tid & 31;
    const int wid  = tid >> 5;
    const int wm   = (wid & 3) * 32;
    const int wn   = (wid >> 2) * 64;
    const int m0 = blockIdx.y * 128;
    const int n0 = blockIdx.x * 128;
    const int g  = lane >> 2;
    const int tg = lane & 3;

    float acc[2][8][4];
    #pragma unroll
    for (int i = 0; i < 2; i++)
        #pragma unroll
        for (int j = 0; j < 8; j++)
            #pragma unroll
            for (int q = 0; q < 4; q++) acc[i][j][q] = 0.0f;

    const int NC = K >> 5;
    gemm_issue(sbase,                  A, W, m0, n0, K, N, 0, tid); CP_COMMIT();
    gemm_issue(sbase + STG_FLOATS * 4, A, W, m0, n0, K, N, 1, tid); CP_COMMIT();

    for (int c = 0; c < NC; c++) {
        CP_WAIT(1);
        __syncthreads();
        if (c + 2 < NC)
            gemm_issue(sbase + (uint32_t)((c + 2) % 3) * (STG_FLOATS * 4),
                       A, W, m0, n0, K, N, c + 2, tid);
        CP_COMMIT();

        float (*As)[36]  = (float(*)[36]) (sm + (c % 3) * STG_FLOATS);
        float (*Bs)[136] = (float(*)[136])(sm + (c % 3) * STG_FLOATS + 4608);
        #pragma unroll
        for (int ks = 0; ks < 4; ks++) {
            int k0 = ks * 8;
            uint32_t a[2][4];
            #pragma unroll
            for (int mi = 0; mi < 2; mi++) {
                int row = wm + mi * 16 + g;
                a[mi][0] = __float_as_uint(As[row    ][k0 + tg]);
                a[mi][1] = __float_as_uint(As[row + 8][k0 + tg]);
                a[mi][2] = __float_as_uint(As[row    ][k0 + tg + 4]);
                a[mi][3] = __float_as_uint(As[row + 8][k0 + tg + 4]);
            }
            #pragma unroll
            for (int nj = 0; nj < 8; nj++) {
                int col = wn + nj * 8 + g;
                uint32_t b0 = __float_as_uint(Bs[k0 + tg    ][col]);
                uint32_t b1 = __float_as_uint(Bs[k0 + tg + 4][col]);
                mma8(acc[0][nj], a[0], b0, b1);
                mma8(acc[1][nj], a[1], b0, b1);
            }
        }
    }

    // epilogue
    #pragma unroll
    for (int mi = 0; mi < 2; mi++) {
        #pragma unroll
        for (int nj = 0; nj < 8; nj++) {
            int r0  = m0 + wm + mi * 16 + g;
            int colG = n0 + wn + nj * 8 + 2 * tg;
            float b0 = bias[colG], b1 = bias[colG + 1];
            float v00 = acc[mi][nj][0] + b0, v01 = acc[mi][nj][1] + b1;
            float v10 = acc[mi][nj][2] + b0, v11 = acc[mi][nj][3] + b1;

            if (EPI == 1) {
                v00 += Rres[(size_t)r0 * N + colG];
                v01 += Rres[(size_t)r0 * N + colG + 1];
                v10 += Rres[(size_t)(r0 + 8) * N + colG];
                v11 += Rres[(size_t)(r0 + 8) * N + colG + 1];
            }
            if (EPI == 2) {
                v00 = 0.5f * v00 * (1.0f + erff(v00 * 0.7071067811865475f));
                v01 = 0.5f * v01 * (1.0f + erff(v01 * 0.7071067811865475f));
                v10 = 0.5f * v10 * (1.0f + erff(v10 * 0.7071067811865475f));
                v11 = 0.5f * v11 * (1.0f + erff(v11 * 0.7071067811865475f));
            }

            if (EPI == 3 || EPI == 5) {
                const bool half = colG >= 512;
                const int coln = colG - (half ? 512 : 0);
                float* Cw = half ? C2 : C;
                if (EPI == 5) {
                    int s0 = r0 & (S - 1);
                    const float* P = half ? P2 : P1;
                    float p00 = P[(size_t)s0 * 512 + coln];
                    float p01 = P[(size_t)s0 * 512 + coln + 1];
                    float p10 = P[(size_t)(s0 + 8) * 512 + coln];
                    float p11 = P[(size_t)(s0 + 8) * 512 + coln + 1];
                    v00 = 0.5f * (v00 + p00);
                    v01 = 0.5f * (v01 + p01);
                    v10 = 0.5f * (v10 + p10);
                    v11 = 0.5f * (v11 + p11);
                }
                if (TF32OUT) {
                    v00 = to_tf32(v00); v01 = to_tf32(v01);
                    v10 = to_tf32(v10); v11 = to_tf32(v11);
                }
                *(float2*)(Cw + (size_t)r0 * 512 + coln)       = make_float2(v00, v01);
                *(float2*)(Cw + (size_t)(r0 + 8) * 512 + coln) = make_float2(v10, v11);
            } else {
                if (TF32OUT) {
                    v00 = to_tf32(v00); v01 = to_tf32(v01);
                    v10 = to_tf32(v10); v11 = to_tf32(v11);
                }
                *(float2*)(C + (size_t)r0 * N + colG)       = make_float2(v00, v01);
                *(float2*)(C + (size_t)(r0 + 8) * N + colG) = make_float2(v10, v11);
            }
        }
    }
}

// ================= fused flash attention v2 =================
// q-tile 64, 128 threads (4 warps x 16 q-rows), single-stage smem, 2-3 CTAs/SM
// scores = (Q+QH)·K^T + Q·HK^T
#define FL2_K    0
#define FL2_HK   4352
#define FL2_V    8704
#define FL2_MASK 13312
#define FL2_PS   13376
#define FL2_SMEM ((13376 + 64*68) * 4)   // 70912 bytes

__device__ __forceinline__ void flash_issue(uint32_t sb, int b, int h, int k0,
                                            int tid, const int* __restrict__ iseq)
{
    const float* Kg  = g_K  + ((size_t)(b * S + k0)) * H + h * DH;
    const float* HKg = g_HK + ((size_t)(b * S + k0)) * H + h * DH;
    const float* Vg  = g_V  + ((size_t)(b * S + k0)) * H + h * DH;
    #pragma unroll
    for (int i = 0; i < 8; i++) {
        int f = tid + i * 128;            // 0..1023
        int r = f >> 4, cq = (f & 15) * 4;
        size_t go = (size_t)r * H + cq;
        cpa16(sb + (uint32_t)(FL2_K  + r * 68 + cq) * 4, Kg  + go);
        cpa16(sb + (uint32_t)(FL2_HK + r * 68 + cq) * 4, HKg + go);
        cpa16(sb + (uint32_t)(FL2_V  + r * 72 + cq) * 4, Vg  + go);
    }
    if (tid < 16)
        cpa16(sb + (uint32_t)(FL2_MASK + tid * 4) * 4, iseq + b * S + k0 + tid * 4);
}

__global__ void __launch_bounds__(128, 3)
flash_attn(const int* __restrict__ iseq)
{
    extern __shared__ __align__(16) float sm[];
    const uint32_t sbase = smem_u32(sm);

    const int bz = blockIdx.y;
    const int b = bz >> 3;
    const int h = bz & 7;
    const int qt = 7 - blockIdx.x;        // heavy tiles first
    const int q0 = qt * 64;
    const int tid = threadIdx.x;
    const int lane = tid & 31;
    const int wid = tid >> 5;             // 0..3
    const int r0 = wid * 16;
    const int g = lane >> 2;
    const int tg = lane & 3;

    const int n_kt = qt + 1;

    // qs = Q+QH (vs K), qo = Q (vs HK)
    uint32_t qs[8][4], qo[8][4];
    {
        const float* Qp  = g_Q  + ((size_t)(b * S + q0 + r0 + g)) * H + h * DH;
        const float* Qp8 = Qp + 8 * H;
        const float* Hp  = g_QH + ((size_t)(b * S + q0 + r0 + g)) * H + h * DH;
        const float* Hp8 = Hp + 8 * H;
        #pragma unroll
        for (int ks = 0; ks < 8; ks++) {
            int c = ks * 8 + tg;
            float q00 = __ldg(Qp  + c),     q10 = __ldg(Qp8 + c);
            float q01 = __ldg(Qp  + c + 4), q11 = __ldg(Qp8 + c + 4);
            float h00 = __ldg(Hp  + c),     h10 = __ldg(Hp8 + c);
            float h01 = __ldg(Hp  + c + 4), h11 = __ldg(Hp8 + c + 4);
            qo[ks][0] = __float_as_uint(q00);
            qo[ks][1] = __float_as_uint(q10);
            qo[ks][2] = __float_as_uint(q01);
            qo[ks][3] = __float_as_uint(q11);
            qs[ks][0] = __float_as_uint(to_tf32(q00 + h00));
            qs[ks][1] = __float_as_uint(to_tf32(q10 + h10));
            qs[ks][2] = __float_as_uint(to_tf32(q01 + h01));
            qs[ks][3] = __float_as_uint(to_tf32(q11 + h11));
        }
    }

    float oacc[8][4];
    #pragma unroll
    for (int i = 0; i < 8; i++)
        #pragma unroll
        for (int q = 0; q < 4; q++) oacc[i][q] = 0.0f;
    float mrow[2] = {-1e30f, -1e30f};
    float lrow[2] = {0.0f, 0.0f};

    float (*Kt )[68] = (float(*)[68])(sm + FL2_K);
    float (*HKt)[68] = (float(*)[68])(sm + FL2_HK);
    float (*Vs )[72] = (float(*)[72])(sm + FL2_V);
    const int* maskv = (const int*)(sm + FL2_MASK);
    float (*Ps)[68]  = (float(*)[68])(sm + FL2_PS);

    flash_issue(sbase, b, h, 0, tid, iseq); CP_COMMIT();

    for (int j = 0; j < n_kt; j++) {
        const int k0 = j * 64;
        const bool causal = (j == qt);

        CP_WAIT(0);
        __syncthreads();

        // ---- scores ----
        float sacc[8][4];
        #pragma unroll
        for (int i = 0; i < 8; i++)
            #pragma unroll
            for (int q = 0; q < 4; q++) sacc[i][q] = 0.0f;

        #pragma unroll
        for (int ks = 0; ks < 8; ks++) {
            int kk = ks * 8;
            #pragma unroll
            for (int nj = 0; nj < 8; nj++) {
                int col = nj * 8 + g;
                uint32_t bk0 = __float_as_uint(Kt [col][kk + tg]);
                uint32_t bk1 = __float_as_uint(Kt [col][kk + tg + 4]);
                uint32_t bh0 = __float_as_uint(HKt[col][kk + tg]);
                uint32_t bh1 = __float_as_uint(HKt[col][kk + tg + 4]);
                mma8(sacc[nj], qs[ks], bk0, bk1);
                mma8(sacc[nj], qo[ks], bh0, bh1);
            }
        }

        // ---- online softmax (warp-local rows), P into smem ----
        #pragma unroll
        for (int h2 = 0; h2 < 2; h2++) {
            int grow = q0 + r0 + g + 8 * h2;
            float sv[16];
            float tmax = -1e30f;
            #pragma unroll
            for (int nj = 0; nj < 8; nj++) {
                #pragma unroll
                for (int cc = 0; cc < 2; cc++) {
                    int c = nj * 8 + 2 * tg + cc;
                    float madd = (!causal || (k0 + c <= grow))
                                 ? ((maskv[c] > 0) ? 0.0f : -10000.0f)
                                 : -10000.0f;
                    float s = sacc[nj][h2 * 2 + cc] * 0.125f + madd;
                    sv[nj * 2 + cc] = s;
                    tmax = fmaxf(tmax, s);
                }
            }
            tmax = fmaxf(tmax, __shfl_xor_sync(0xffffffffu, tmax, 1));
            tmax = fmaxf(tmax, __shfl_xor_sync(0xffffffffu, tmax, 2));
            float mnew = fmaxf(mrow[h2], tmax);
            float scale = __expf(mrow[h2] - mnew);
            mrow[h2] = mnew;
            float rs = 0.0f;
            #pragma unroll
            for (int nj = 0; nj < 8; nj++) {
                float p0 = __expf(sv[nj * 2]     - mnew);
                float p1 = __expf(sv[nj * 2 + 1] - mnew);
                rs += p0 + p1;
                *(float2*)&Ps[r0 + g + 8 * h2][nj * 8 + 2 * tg] =
                    make_float2(to_tf32(p0), to_tf32(p1));
            }
            rs += __shfl_xor_sync(0xffffffffu, rs, 1);
            rs += __shfl_xor_sync(0xffffffffu, rs, 2);
            lrow[h2] = lrow[h2] * scale + rs;
            #pragma unroll
            for (int nd = 0; nd < 8; nd++) {
                oacc[nd][h2 * 2]     *= scale;
                oacc[nd][h2 * 2 + 1] *= scale;
            }
        }
        __syncwarp();

        // ---- O += P @ V ----
        #pragma unroll
        for (int ks = 0; ks < 8; ks++) {
            int kk = ks * 8;
            uint32_t pa[4];
            pa[0] = __float_as_uint(Ps[r0 + g    ][kk + tg]);
            pa[1] = __float_as_uint(Ps[r0 + g + 8][kk + tg]);
            pa[2] = __float_as_uint(Ps[r0 + g    ][kk + tg + 4]);
            pa[3] = __float_as_uint(Ps[r0 + g + 8][kk + tg + 4]);
            #pragma unroll
            for (int nd = 0; nd < 8; nd++) {
                int col = nd * 8 + g;
                uint32_t b0 = __float_as_uint(Vs[kk + tg    ][col]);
                uint32_t b1 = __float_as_uint(Vs[kk + tg + 4][col]);
                mma8(oacc[nd], pa, b0, b1);
            }
        }

        __syncthreads();   // all warps done with K/HK/V before overwrite
        if (j + 1 < n_kt) {
            flash_issue(sbase, b, h, (j + 1) * 64, tid, iseq);
        }
        CP_COMMIT();
    }

    float inv0 = 1.0f / lrow[0];
    float inv1 = 1.0f / lrow[1];
    size_t base = ((size_t)(b * S + q0 + r0 + g)) * H + h * DH;
    #pragma unroll
    for (int nd = 0; nd < 8; nd++) {
        int c = nd * 8 + 2 * tg;
        *(float2*)(g_CTX + base + c) =
            make_float2(to_tf32(oacc[nd][0] * inv0), to_tf32(oacc[nd][1] * inv0));
        *(float2*)(g_CTX + base + 8 * H + c) =
            make_float2(to_tf32(oacc[nd][2] * inv1), to_tf32(oacc[nd][3] * inv1));
    }
}

// ---------------- LayerNorm -----------------
template<int ROUND>
__global__ __launch_bounds__(256)
void ln_kernel(const float* __restrict__ in, const float* __restrict__ gam,
               const float* __restrict__ bet, float* __restrict__ out)
{
    size_t row = blockIdx.x;
    const float* p = in + row * H;
    int t = threadIdx.x;
    float x0 = p[t], x1 = p[t + 256];

    __shared__ float r1[8], r2[8];
    float s = x0 + x1;
    float sq = x0 * x0 + x1 * x1;
    #pragma unroll
    for (int o = 16; o; o >>= 1) {
        s  += __shfl_xor_sync(0xffffffffu, s, o);
        sq += __shfl_xor_sync(0xffffffffu, sq, o);
    }
    if ((t & 31) == 0) { r1[t >> 5] = s; r2[t >> 5] = sq; }
    __syncthreads();
    if (t == 0) {
        float S1 = 0.0f, S2 = 0.0f;
        #pragma unroll
        for (int i = 0; i < 8; i++) { S1 += r1[i]; S2 += r2[i]; }
        r1[0] = S1; r2[0] = S2;
    }
    __syncthreads();
    float mean = r1[0] * (1.0f / (float)H);
    float var  = r2[0] * (1.0f / (float)H) - mean * mean;
    float rstd = rsqrtf(var + 1e-12f);
    float o0 = (x0 - mean) * rstd * gam[t]       + bet[t];
    float o1 = (x1 - mean) * rstd * gam[t + 256] + bet[t + 256];
    if (ROUND) { o0 = to_tf32(o0); o1 = to_tf32(o1); }
    out[row * H + t]       = o0;
    out[row * H + t + 256] = o1;
}

// ---------------- launcher ----------------
extern "C" void kernel_launch(void* const* d_in, const int* in_sizes, int n_in,
                              void* d_out, int out_size)
{
    const float* x    = (const float*)d_in[0];
    const float* vin  = (const float*)d_in[1];
    const float* beha = (const float*)d_in[2];
    const float* pos  = (const float*)d_in[3];
    const float* Wq   = (const float*)d_in[4];
    const float* bq   = (const float*)d_in[5];
    const float* Wk   = (const float*)d_in[6];
    const float* bk   = (const float*)d_in[7];
    const float* Wv   = (const float*)d_in[8];
    const float* bv   = (const float*)d_in[9];
    const float* Wpk  = (const float*)d_in[10];
    const float* bpk  = (const float*)d_in[11];
    const float* Wpq  = (const float*)d_in[12];
    const float* bpq  = (const float*)d_in[13];
    const float* Wbk  = (const float*)d_in[14];
    const float* bbk  = (const float*)d_in[15];
    const float* Wbq  = (const float*)d_in[16];
    const float* bbq  = (const float*)d_in[17];
    const float* Wd   = (const float*)d_in[18];
    const float* bd   = (const float*)d_in[19];
    const float* ln_g = (const float*)d_in[20];
    const float* ln_b = (const float*)d_in[21];
    const float* W1   = (const float*)d_in[22];
    const float* b1   = (const float*)d_in[23];
    const float* W2   = (const float*)d_in[24];
    const float* b2   = (const float*)d_in[25];
    const float* ln2g = (const float*)d_in[26];
    const float* ln2b = (const float*)d_in[27];
    const int*   iseq = (const int*)d_in[28];
    float* out = (float*)d_out;

    float *pQ, *pK, *pV, *pHK, *pQH, *pPK, *pPQ, *pCTX, *pATT, *pAO, *pH1, *pWT;
    float *pBQK, *pBB2, *pBPP;
    cudaGetSymbolAddress((void**)&pQ,   g_Q);
    cudaGetSymbolAddress((void**)&pK,   g_K);
    cudaGetSymbolAddress((void**)&pV,   g_V);
    cudaGetSymbolAddress((void**)&pHK,  g_HK);
    cudaGetSymbolAddress((void**)&pQH,  g_QH);
    cudaGetSymbolAddress((void**)&pPK,  g_PK);
    cudaGetSymbolAddress((void**)&pPQ,  g_PQ);
    cudaGetSymbolAddress((void**)&pCTX, g_CTX);
    cudaGetSymbolAddress((void**)&pATT, g_ATT);
    cudaGetSymbolAddress((void**)&pAO,  g_AO);
    cudaGetSymbolAddress((void**)&pH1,  g_H1);
    cudaGetSymbolAddress((void**)&pWT,  g_WT);
    cudaGetSymbolAddress((void**)&pBQK, g_BQK);
    cudaGetSymbolAddress((void**)&pBB2, g_BB2);
    cudaGetSymbolAddress((void**)&pBPP, g_BPP);

    cudaFuncSetAttribute(mma_gemm<1,0>, cudaFuncAttributeMaxDynamicSharedMemorySize, GEMM_SMEM);
    cudaFuncSetAttribute(mma_gemm<1,1>, cudaFuncAttributeMaxDynamicSharedMemorySize, GEMM_SMEM);
    cudaFuncSetAttribute(mma_gemm<2,1>, cudaFuncAttributeMaxDynamicSharedMemorySize, GEMM_SMEM);
    cudaFuncSetAttribute(mma_gemm<3,0>, cudaFuncAttributeMaxDynamicSharedMemorySize, GEMM_SMEM);
    cudaFuncSetAttribute(mma_gemm<3,1>, cudaFuncAttributeMaxDynamicSharedMemorySize, GEMM_SMEM);
    cudaFuncSetAttribute(mma_gemm<5,1>, cudaFuncAttributeMaxDynamicSharedMemorySize, GEMM_SMEM);
    cudaFuncSetAttribute(flash_attn, cudaFuncAttributeMaxDynamicSharedMemorySize, FL2_SMEM);

    // static side streams/events for fork-join (created once; graph-capture safe)
    static cudaStream_t s1 = nullptr, s2 = nullptr;
    static cudaEvent_t evFork = nullptr, evV = nullptr, evS2 = nullptr;
    if (!s1) {
        cudaStreamCreateWithFlags(&s1, cudaStreamNonBlocking);
        cudaStreamCreateWithFlags(&s2, cudaStreamNonBlocking);
        cudaEventCreateWithFlags(&evFork, cudaEventDisableTiming);
        cudaEventCreateWithFlags(&evV,    cudaEventDisableTiming);
        cudaEventCreateWithFlags(&evS2,   cudaEventDisableTiming);
    }

    dim3 blk(256);

    // ---- prep (weights + biases) ----
    prep_kernel<<<(PR_END + 255) / 256, blk>>>(Wv, Wd, W1, W2,
                                               Wq, Wk, Wbk, Wbq, Wpk, Wpq,
                                               bq, bk, bbk, bbq, bpk, bpq);

    // fork: V on s1; pos -> BKBQ on s2; Q|K on default. All independent.
    cudaEventRecord(evFork, 0);
    cudaStreamWaitEvent(s1, evFork, 0);
    cudaStreamWaitEvent(s2, evFork, 0);

    dim3 gProj(512 / 128, BS / 128);
    mma_gemm<1,1><<<gProj, blk, GEMM_SMEM, s1>>>(vin, pWT + WT_V, bv, vin, nullptr, nullptr, pV, nullptr, BS, H, H);
    cudaEventRecord(evV, s1);

    dim3 gPos(1024 / 128, S / 128);
    dim3 gQK(1024 / 128, BS / 128);
    mma_gemm<3,0><<<gPos, blk, GEMM_SMEM, s2>>>(pos, pWT + WT_PKPQ, pBPP, nullptr, nullptr, nullptr, pPK, pPQ, S, 1024, H);
    mma_gemm<5,1><<<gQK, blk, GEMM_SMEM, s2>>>(beha, pWT + WT_BKBQ, pBB2, nullptr, pPK, pPQ, pHK, pQH, BS, 1024, H);
    cudaEventRecord(evS2, s2);

    mma_gemm<3,1><<<gQK, blk, GEMM_SMEM>>>(x, pWT + WT_QK, pBQK, nullptr, nullptr, nullptr, pQ, pK, BS, 1024, H);

    // join before flash (needs Q,K,HK,QH,V)
    cudaStreamWaitEvent(0, evS2, 0);
    cudaStreamWaitEvent(0, evV, 0);

    // fused attention (q-tile 64, 128 threads)
    flash_attn<<<dim3(8, B * NH), dim3(128), FL2_SMEM>>>(iseq);

    mma_gemm<1,0><<<gProj, blk, GEMM_SMEM>>>(pCTX, pWT + WT_D, bd, x, nullptr, nullptr, pATT, nullptr, BS, H, H);
    ln_kernel<1><<<BS, blk>>>(pATT, ln_g, ln_b, pAO);

    dim3 gF1(INNER / 128, BS / 128);
    mma_gemm<2,1><<<gF1, blk, GEMM_SMEM>>>(pAO, pWT + WT_1, b1, nullptr, nullptr, nullptr, pH1, nullptr, BS, INNER, H);
    mma_gemm<1,0><<<gProj, blk, GEMM_SMEM>>>(pH1, pWT + WT_2, b2, pAO, nullptr, nullptr, pATT, nullptr, BS, H, INNER);
    ln_kernel<0><<<BS, blk>>>(pATT, ln2g, ln2b, out);
}

// round 14
// speedup vs baseline: 1.0680x; 1.0531x over previous
#include <cuda_runtime.h>
#include <math.h>
#include <stdint.h>

// ---------------- problem constants ----------------
#define B 32
#define S 512
#define H 512
#define NH 8
#define DH 64
#define INNER 2048
#define BS (B*S)            // 16384
#define BSH ((size_t)B*S*H) // 8388608

// ---------------- scratch ----------------
__device__ float g_Q  [BSH];
__device__ float g_K  [BSH];
__device__ float g_V  [BSH];
__device__ float g_HK [BSH];   // 0.5*(bhk + pk)
__device__ float g_QH [BSH];   // 0.5*(bhq + pq)
__device__ float g_PK [S*H];
__device__ float g_PQ [S*H];
__device__ float g_CTX[BSH];
__device__ float g_ATT[BSH];
__device__ float g_AO [BSH];
__device__ float g_H1 [(size_t)BS*INNER];
__device__ float g_WT [4194304];   // tf32 weights pool
__device__ float g_BQK[1024];      // packed bq|bk
__device__ float g_BB2[1024];      // packed bbk|bbq

// offsets into g_WT (floats)
#define WT_QK   0          // 512x1024
#define WT_BKBQ 524288     // 512x1024
#define WT_V    1572864    // 512x512
#define WT_D    1835008    // 512x512
#define WT_1    2097152    // 512x2048
#define WT_2    3145728    // 2048x512

// ---------------- helpers ----------------
__device__ __forceinline__ uint32_t smem_u32(const void* p) {
    uint32_t a;
    asm("{ .reg .u64 t; cvta.to.shared.u64 t, %1; cvt.u32.u64 %0, t; }"
        : "=r"(a) : "l"(p));
    return a;
}

__device__ __forceinline__ float to_tf32(float x) {
    float r;
    asm("cvt.rna.tf32.f32 %0, %1;" : "=f"(r) : "f"(x));
    return r;
}

__device__ __forceinline__ void mma8(float* c, const uint32_t* a, uint32_t b0, uint32_t b1) {
    asm volatile(
        "mma.sync.aligned.m16n8k8.row.col.f32.tf32.tf32.f32 "
        "{%0,%1,%2,%3}, {%4,%5,%6,%7}, {%8,%9}, {%0,%1,%2,%3};"
        : "+f"(c[0]), "+f"(c[1]), "+f"(c[2]), "+f"(c[3])
        : "r"(a[0]), "r"(a[1]), "r"(a[2]), "r"(a[3]), "r"(b0), "r"(b1));
}

// A-fragment loader: 4 8x8(b16-view) tiles = a[0..3] of m16n8k8 tf32 A
__device__ __forceinline__ void ldsm4(uint32_t* r, uint32_t addr) {
    asm volatile("ldmatrix.sync.aligned.m8n8.x4.shared.b16 {%0,%1,%2,%3}, [%4];"
        : "=r"(r[0]), "=r"(r[1]), "=r"(r[2]), "=r"(r[3]) : "r"(addr));
}

__device__ __forceinline__ void cpa16(uint32_t saddr, const void* gaddr) {
    asm volatile("cp.async.cg.shared.global [%0], [%1], 16;" :: "r"(saddr), "l"(gaddr));
}
#define CP_COMMIT() asm volatile("cp.async.commit_group;" ::: "memory")
#define CP_WAIT(n)  asm volatile("cp.async.wait_group %0;" :: "n"(n) : "memory")

// ================= unified prep kernel (weights only) =================
__device__ __forceinline__ float4 rnd4(float4 v) {
    v.x = to_tf32(v.x); v.y = to_tf32(v.y);
    v.z = to_tf32(v.z); v.w = to_tf32(v.w);
    return v;
}

// flat f4 ranges
#define PR_WV   0
#define PR_WD   65536
#define PR_W1   131072
#define PR_W2   393216
#define PR_QK   655360
#define PR_BKBQ 786432
#define PR_END  917504

__global__ void prep_kernel(const float* __restrict__ Wv, const float* __restrict__ Wd,
                            const float* __restrict__ W1, const float* __restrict__ W2,
                            const float* __restrict__ Wq,  const float* __restrict__ Wk,
                            const float* __restrict__ Wbk, const float* __restrict__ Wbq,
                            const float* __restrict__ bq,  const float* __restrict__ bk,
                            const float* __restrict__ bbk, const float* __restrict__ bbq)
{
    int i = blockIdx.x * blockDim.x + threadIdx.x;
    if (i >= PR_END) return;

    if (i < PR_QK) {
        const float* p; float* q; int off;
        if (i < PR_WD)       { p = Wv;   q = g_WT + WT_V;    off = i; }
        else if (i < PR_W1)  { p = Wd;   q = g_WT + WT_D;    off = i - PR_WD; }
        else if (i < PR_W2)  { p = W1;   q = g_WT + WT_1;    off = i - PR_W1; }
        else                 { p = W2;   q = g_WT + WT_2;    off = i - PR_W2; }
        ((float4*)q)[off] = rnd4(((const float4*)p)[off]);
    } else {
        const float *A1, *A2, *c1, *c2; float *outW, *outB; int local;
        if (i < PR_BKBQ) { A1 = Wq;  A2 = Wk;  c1 = bq;  c2 = bk;  outW = g_WT + WT_QK;   outB = g_BQK; local = i - PR_QK; }
        else             { A1 = Wbk; A2 = Wbq; c1 = bbk; c2 = bbq; outW = g_WT + WT_BKBQ; outB = g_BB2; local = i - PR_BKBQ; }
        int row = local >> 8;
        int c4 = local & 255;
        const float* src = (c4 < 128) ? (A1 + (size_t)row * 512 + c4 * 4)
                                      : (A2 + (size_t)row * 512 + (c4 - 128) * 4);
        ((float4*)outW)[local] = rnd4(*(const float4*)src);
        if (local < 256) {
            int c = local * 4;
            const float* sb = (c < 512) ? (c1 + c) : (c2 + c - 512);
            *(float4*)(outB + c) = *(const float4*)sb;
        }
    }
}

// ================= mma.sync tf32 GEMM, 128x128 tile, cp.async 3-stage ======
// EPI: 0 bias, 1 +residual, 2 gelu, 3 split write (C/C2 512-halves),
//      5 split combine: both halves = 0.5*(acc+bias+Psel)
#define STG_FLOATS 8960                 // A 128*36 + B 32*136
#define GEMM_SMEM (3*STG_FLOATS*4)      // 107520 bytes

__device__ __forceinline__ void gemm_issue(uint32_t sstage,
                                           const float* __restrict__ A,
                                           const float* __restrict__ W,
                                           int m0, int n0, int K, int N, int c, int tid)
{
    const float* Ag = A + (size_t)m0 * K + c * 32;
    const float* Wg = W + (size_t)(c * 32) * N + n0;
    #pragma unroll
    for (int i = 0; i < 4; i++) {
        int f = tid + i * 256;
        int r = f >> 3, kq = (f & 7) * 4;
        cpa16(sstage + (uint32_t)(r * 36 + kq) * 4, Ag + (size_t)r * K + kq);
    }
    #pragma unroll
    for (int i = 0; i < 4; i++) {
        int f = tid + i * 256;
        int kr = f >> 5, nq = (f & 31) * 4;
        cpa16(sstage + (uint32_t)(4608 + kr * 136 + nq) * 4, Wg + (size_t)kr * N + nq);
    }
}

template<int EPI, int TF32OUT>
__global__ void __launch_bounds__(256, 2)
mma_gemm(const float* __restrict__ A, const float* __restrict__ W,
         const float* __restrict__ bias, const float* __restrict__ Rres,
         const float* __restrict__ P1, const float* __restrict__ P2,
         float* __restrict__ C, float* __restrict__ C2,
         int M, int N, int K)
{
    extern __shared__ __align__(16) float sm[];
    const uint32_t sbase = smem_u32(sm);
    const int tid  = threadIdx.x;
    const int lane = tid & 31;
    const int wid  = tid >> 5;
    const int wm   = (wid & 3) * 32;
    const int wn   = (wid >> 2) * 64;
    const int m0 = blockIdx.y * 128;
    const int n0 = blockIdx.x * 128;
    const int g  = lane >> 2;
    const int tg = lane & 3;

    // per-thread A-LDSM base offset within a stage (bytes):
    // row = wm + (lane&15), col16 = (lane>>4)*4 floats
    const uint32_t aoff = (uint32_t)((wm + (lane & 15)) * 36 + ((lane >> 4) << 2)) * 4;

    float acc[2][8][4];
    #pragma unroll
    for (int i = 0; i < 2; i++)
        #pragma unroll
        for (int j = 0; j < 8; j++)
            #pragma unroll
            for (int q = 0; q < 4; q++) acc[i][j][q] = 0.0f;

    const int NC = K >> 5;
    gemm_issue(sbase,                  A, W, m0, n0, K, N, 0, tid); CP_COMMIT();
    gemm_issue(sbase + STG_FLOATS * 4, A, W, m0, n0, K, N, 1, tid); CP_COMMIT();

    for (int c = 0; c < NC; c++) {
        CP_WAIT(1);
        __syncthreads();
        if (c + 2 < NC)
            gemm_issue(sbase + (uint32_t)((c + 2) % 3) * (STG_FLOATS * 4),
                       A, W, m0, n0, K, N, c + 2, tid);
        CP_COMMIT();

        float (*Bs)[136] = (float(*)[136])(sm + (c % 3) * STG_FLOATS + 4608);
        const uint32_t abase = sbase + (uint32_t)((c % 3) * STG_FLOATS) * 4 + aoff;
        #pragma unroll
        for (int ks = 0; ks < 4; ks++) {
            int k0 = ks * 8;
            uint32_t a[2][4];
            ldsm4(a[0], abase + ks * 32);
            ldsm4(a[1], abase + ks * 32 + 16 * 36 * 4);
            #pragma unroll
            for (int nj = 0; nj < 8; nj++) {
                int col = wn + nj * 8 + g;
                uint32_t b0 = __float_as_uint(Bs[k0 + tg    ][col]);
                uint32_t b1 = __float_as_uint(Bs[k0 + tg + 4][col]);
                mma8(acc[0][nj], a[0], b0, b1);
                mma8(acc[1][nj], a[1], b0, b1);
            }
        }
    }

    // epilogue
    #pragma unroll
    for (int mi = 0; mi < 2; mi++) {
        #pragma unroll
        for (int nj = 0; nj < 8; nj++) {
            int r0  = m0 + wm + mi * 16 + g;
            int colG = n0 + wn + nj * 8 + 2 * tg;
            float b0 = bias[colG], b1 = bias[colG + 1];
            float v00 = acc[mi][nj][0] + b0, v01 = acc[mi][nj][1] + b1;
            float v10 = acc[mi][nj][2] + b0, v11 = acc[mi][nj][3] + b1;

            if (EPI == 1) {
                v00 += Rres[(size_t)r0 * N + colG];
                v01 += Rres[(size_t)r0 * N + colG + 1];
                v10 += Rres[(size_t)(r0 + 8) * N + colG];
                v11 += Rres[(size_t)(r0 + 8) * N + colG + 1];
            }
            if (EPI == 2) {
                v00 = 0.5f * v00 * (1.0f + erff(v00 * 0.7071067811865475f));
                v01 = 0.5f * v01 * (1.0f + erff(v01 * 0.7071067811865475f));
                v10 = 0.5f * v10 * (1.0f + erff(v10 * 0.7071067811865475f));
                v11 = 0.5f * v11 * (1.0f + erff(v11 * 0.7071067811865475f));
            }

            if (EPI == 3 || EPI == 5) {
                const bool half = colG >= 512;
                const int coln = colG - (half ? 512 : 0);
                float* Cw = half ? C2 : C;
                if (EPI == 5) {
                    int s0 = r0 & (S - 1);
                    const float* P = half ? P2 : P1;
                    float p00 = P[(size_t)s0 * 512 + coln];
                    float p01 = P[(size_t)s0 * 512 + coln + 1];
                    float p10 = P[(size_t)(s0 + 8) * 512 + coln];
                    float p11 = P[(size_t)(s0 + 8) * 512 + coln + 1];
                    v00 = 0.5f * (v00 + p00);
                    v01 = 0.5f * (v01 + p01);
                    v10 = 0.5f * (v10 + p10);
                    v11 = 0.5f * (v11 + p11);
                }
                if (TF32OUT) {
                    v00 = to_tf32(v00); v01 = to_tf32(v01);
                    v10 = to_tf32(v10); v11 = to_tf32(v11);
                }
                *(float2*)(Cw + (size_t)r0 * 512 + coln)       = make_float2(v00, v01);
                *(float2*)(Cw + (size_t)(r0 + 8) * 512 + coln) = make_float2(v10, v11);
            } else {
                if (TF32OUT) {
                    v00 = to_tf32(v00); v01 = to_tf32(v01);
                    v10 = to_tf32(v10); v11 = to_tf32(v11);
                }
                *(float2*)(C + (size_t)r0 * N + colG)       = make_float2(v00, v01);
                *(float2*)(C + (size_t)(r0 + 8) * N + colG) = make_float2(v10, v11);
            }
        }
    }
}

// ================= fused flash attention v2 =================
// q-tile 64, 128 threads (4 warps x 16 q-rows), single-stage smem
// scores = (Q+QH)·K^T + Q·HK^T
#define FL2_K    0
#define FL2_HK   4352
#define FL2_V    8704
#define FL2_MASK 13312
#define FL2_PS   13376
#define FL2_SMEM ((13376 + 64*68) * 4)   // 70912 bytes

__device__ __forceinline__ void flash_issue(uint32_t sb, int b, int h, int k0,
                                            int tid, const int* __restrict__ iseq)
{
    const float* Kg  = g_K  + ((size_t)(b * S + k0)) * H + h * DH;
    const float* HKg = g_HK + ((size_t)(b * S + k0)) * H + h * DH;
    const float* Vg  = g_V  + ((size_t)(b * S + k0)) * H + h * DH;
    #pragma unroll
    for (int i = 0; i < 8; i++) {
        int f = tid + i * 128;
        int r = f >> 4, cq = (f & 15) * 4;
        size_t go = (size_t)r * H + cq;
        cpa16(sb + (uint32_t)(FL2_K  + r * 68 + cq) * 4, Kg  + go);
        cpa16(sb + (uint32_t)(FL2_HK + r * 68 + cq) * 4, HKg + go);
        cpa16(sb + (uint32_t)(FL2_V  + r * 72 + cq) * 4, Vg  + go);
    }
    if (tid < 16)
        cpa16(sb + (uint32_t)(FL2_MASK + tid * 4) * 4, iseq + b * S + k0 + tid * 4);
}

__global__ void __launch_bounds__(128, 3)
flash_attn(const int* __restrict__ iseq)
{
    extern __shared__ __align__(16) float sm[];
    const uint32_t sbase = smem_u32(sm);

    const int bz = blockIdx.y;
    const int b = bz >> 3;
    const int h = bz & 7;
    const int qt = 7 - blockIdx.x;
    const int q0 = qt * 64;
    const int tid = threadIdx.x;
    const int lane = tid & 31;
    const int wid = tid >> 5;
    const int r0 = wid * 16;
    const int g = lane >> 2;
    const int tg = lane & 3;

    const int n_kt = qt + 1;

    // qs = Q+QH (vs K), qo = Q (vs HK)
    uint32_t qs[8][4], qo[8][4];
    {
        const float* Qp  = g_Q  + ((size_t)(b * S + q0 + r0 + g)) * H + h * DH;
        const float* Qp8 = Qp + 8 * H;
        const float* Hp  = g_QH + ((size_t)(b * S + q0 + r0 + g)) * H + h * DH;
        const float* Hp8 = Hp + 8 * H;
        #pragma unroll
        for (int ks = 0; ks < 8; ks++) {
            int c = ks * 8 + tg;
            float q00 = __ldg(Qp  + c),     q10 = __ldg(Qp8 + c);
            float q01 = __ldg(Qp  + c + 4), q11 = __ldg(Qp8 + c + 4);
            float h00 = __ldg(Hp  + c),     h10 = __ldg(Hp8 + c);
            float h01 = __ldg(Hp  + c + 4), h11 = __ldg(Hp8 + c + 4);
            qo[ks][0] = __float_as_uint(q00);
            qo[ks][1] = __float_as_uint(q10);
            qo[ks][2] = __float_as_uint(q01);
            qo[ks][3] = __float_as_uint(q11);
            qs[ks][0] = __float_as_uint(to_tf32(q00 + h00));
            qs[ks][1] = __float_as_uint(to_tf32(q10 + h10));
            qs[ks][2] = __float_as_uint(to_tf32(q01 + h01));
            qs[ks][3] = __float_as_uint(to_tf32(q11 + h11));
        }
    }

    float oacc[8][4];
    #pragma unroll
    for (int i = 0; i < 8; i++)
        #pragma unroll
        for (int q = 0; q < 4; q++) oacc[i][q] = 0.0f;
    float mrow[2] = {-1e30f, -1e30f};
    float lrow[2] = {0.0f, 0.0f};

    float (*Kt )[68] = (float(*)[68])(sm + FL2_K);
    float (*HKt)[68] = (float(*)[68])(sm + FL2_HK);
    float (*Vs )[72] = (float(*)[72])(sm + FL2_V);
    const int* maskv = (const int*)(sm + FL2_MASK);
    float (*Ps)[68]  = (float(*)[68])(sm + FL2_PS);

    // P-fragment LDSM base (A-fragment pattern over Ps, stride 68)
    const uint32_t pbase = sbase +
        (uint32_t)(FL2_PS + (r0 + (lane & 15)) * 68 + ((lane >> 4) << 2)) * 4;

    flash_issue(sbase, b, h, 0, tid, iseq); CP_COMMIT();

    for (int j = 0; j < n_kt; j++) {
        const int k0 = j * 64;
        const bool causal = (j == qt);

        CP_WAIT(0);
        __syncthreads();

        // ---- scores ----
        float sacc[8][4];
        #pragma unroll
        for (int i = 0; i < 8; i++)
            #pragma unroll
            for (int q = 0; q < 4; q++) sacc[i][q] = 0.0f;

        #pragma unroll
        for (int ks = 0; ks < 8; ks++) {
            int kk = ks * 8;
            #pragma unroll
            for (int nj = 0; nj < 8; nj++) {
                int col = nj * 8 + g;
                uint32_t bk0 = __float_as_uint(Kt [col][kk + tg]);
                uint32_t bk1 = __float_as_uint(Kt [col][kk + tg + 4]);
                uint32_t bh0 = __float_as_uint(HKt[col][kk + tg]);
                uint32_t bh1 = __float_as_uint(HKt[col][kk + tg + 4]);
                mma8(sacc[nj], qs[ks], bk0, bk1);
                mma8(sacc[nj], qo[ks], bh0, bh1);
            }
        }

        // ---- online softmax (warp-local rows), P into smem ----
        #pragma unroll
        for (int h2 = 0; h2 < 2; h2++) {
            int grow = q0 + r0 + g + 8 * h2;
            float sv[16];
            float tmax = -1e30f;
            #pragma unroll
            for (int nj = 0; nj < 8; nj++) {
                #pragma unroll
                for (int cc = 0; cc < 2; cc++) {
                    int c = nj * 8 + 2 * tg + cc;
                    float madd = (!causal || (k0 + c <= grow))
                                 ? ((maskv[c] > 0) ? 0.0f : -10000.0f)
                                 : -10000.0f;
                    float s = sacc[nj][h2 * 2 + cc] * 0.125f + madd;
                    sv[nj * 2 + cc] = s;
                    tmax = fmaxf(tmax, s);
                }
            }
            tmax = fmaxf(tmax, __shfl_xor_sync(0xffffffffu, tmax, 1));
            tmax = fmaxf(tmax, __shfl_xor_sync(0xffffffffu, tmax, 2));
            float mnew = fmaxf(mrow[h2], tmax);
            float scale = __expf(mrow[h2] - mnew);
            mrow[h2] = mnew;
            float rs = 0.0f;
            #pragma unroll
            for (int nj = 0; nj < 8; nj++) {
                float p0 = __expf(sv[nj * 2]     - mnew);
                float p1 = __expf(sv[nj * 2 + 1] - mnew);
                rs += p0 + p1;
                *(float2*)&Ps[r0 + g + 8 * h2][nj * 8 + 2 * tg] =
                    make_float2(to_tf32(p0), to_tf32(p1));
            }
            rs += __shfl_xor_sync(0xffffffffu, rs, 1);
            rs += __shfl_xor_sync(0xffffffffu, rs, 2);
            lrow[h2] = lrow[h2] * scale + rs;
            #pragma unroll
            for (int nd = 0; nd < 8; nd++) {
                oacc[nd][h2 * 2]     *= scale;
                oacc[nd][h2 * 2 + 1] *= scale;
            }
        }
        __syncwarp();

        // ---- O += P @ V ----
        #pragma unroll
        for (int ks = 0; ks < 8; ks++) {
            int kk = ks * 8;
            uint32_t pa[4];
            ldsm4(pa, pbase + ks * 32);
            #pragma unroll
            for (int nd = 0; nd < 8; nd++) {
                int col = nd * 8 + g;
                uint32_t b0 = __float_as_uint(Vs[kk + tg    ][col]);
                uint32_t b1 = __float_as_uint(Vs[kk + tg + 4][col]);
                mma8(oacc[nd], pa, b0, b1);
            }
        }

        __syncthreads();   // all warps done with K/HK/V before overwrite
        if (j + 1 < n_kt) {
            flash_issue(sbase, b, h, (j + 1) * 64, tid, iseq);
        }
        CP_COMMIT();
    }

    float inv0 = 1.0f / lrow[0];
    float inv1 = 1.0f / lrow[1];
    size_t base = ((size_t)(b * S + q0 + r0 + g)) * H + h * DH;
    #pragma unroll
    for (int nd = 0; nd < 8; nd++) {
        int c = nd * 8 + 2 * tg;
        *(float2*)(g_CTX + base + c) =
            make_float2(to_tf32(oacc[nd][0] * inv0), to_tf32(oacc[nd][1] * inv0));
        *(float2*)(g_CTX + base + 8 * H + c) =
            make_float2(to_tf32(oacc[nd][2] * inv1), to_tf32(oacc[nd][3] * inv1));
    }
}

// ---------------- LayerNorm -----------------
template<int ROUND>
__global__ __launch_bounds__(256)
void ln_kernel(const float* __restrict__ in, const float* __restrict__ gam,
               const float* __restrict__ bet, float* __restrict__ out)
{
    size_t row = blockIdx.x;
    const float* p = in + row * H;
    int t = threadIdx.x;
    float x0 = p[t], x1 = p[t + 256];

    __shared__ float r1[8], r2[8];
    float s = x0 + x1;
    float sq = x0 * x0 + x1 * x1;
    #pragma unroll
    for (int o = 16; o; o >>= 1) {
        s  += __shfl_xor_sync(0xffffffffu, s, o);
        sq += __shfl_xor_sync(0xffffffffu, sq, o);
    }
    if ((t & 31) == 0) { r1[t >> 5] = s; r2[t >> 5] = sq; }
    __syncthreads();
    if (t == 0) {
        float S1 = 0.0f, S2 = 0.0f;
        #pragma unroll
        for (int i = 0; i < 8; i++) { S1 += r1[i]; S2 += r2[i]; }
        r1[0] = S1; r2[0] = S2;
    }
    __syncthreads();
    float mean = r1[0] * (1.0f / (float)H);
    float var  = r2[0] * (1.0f / (float)H) - mean * mean;
    float rstd = rsqrtf(var + 1e-12f);
    float o0 = (x0 - mean) * rstd * gam[t]       + bet[t];
    float o1 = (x1 - mean) * rstd * gam[t + 256] + bet[t + 256];
    if (ROUND) { o0 = to_tf32(o0); o1 = to_tf32(o1); }
    out[row * H + t]       = o0;
    out[row * H + t + 256] = o1;
}

// ---------------- launcher ----------------
extern "C" void kernel_launch(void* const* d_in, const int* in_sizes, int n_in,
                              void* d_out, int out_size)
{
    const float* x    = (const float*)d_in[0];
    const float* vin  = (const float*)d_in[1];
    const float* beha = (const float*)d_in[2];
    const float* pos  = (const float*)d_in[3];
    const float* Wq   = (const float*)d_in[4];
    const float* bq   = (const float*)d_in[5];
    const float* Wk   = (const float*)d_in[6];
    const float* bk   = (const float*)d_in[7];
    const float* Wv   = (const float*)d_in[8];
    const float* bv   = (const float*)d_in[9];
    const float* Wpk  = (const float*)d_in[10];
    const float* bpk  = (const float*)d_in[11];
    const float* Wpq  = (const float*)d_in[12];
    const float* bpq  = (const float*)d_in[13];
    const float* Wbk  = (const float*)d_in[14];
    const float* bbk  = (const float*)d_in[15];
    const float* Wbq  = (const float*)d_in[16];
    const float* bbq  = (const float*)d_in[17];
    const float* Wd   = (const float*)d_in[18];
    const float* bd   = (const float*)d_in[19];
    const float* ln_g = (const float*)d_in[20];
    const float* ln_b = (const float*)d_in[21];
    const float* W1   = (const float*)d_in[22];
    const float* b1   = (const float*)d_in[23];
    const float* W2   = (const float*)d_in[24];
    const float* b2   = (const float*)d_in[25];
    const float* ln2g = (const float*)d_in[26];
    const float* ln2b = (const float*)d_in[27];
    const int*   iseq = (const int*)d_in[28];
    float* out = (float*)d_out;

    float *pQ, *pK, *pV, *pHK, *pQH, *pPK, *pPQ, *pCTX, *pATT, *pAO, *pH1, *pWT;
    float *pBQK, *pBB2;
    cudaGetSymbolAddress((void**)&pQ,   g_Q);
    cudaGetSymbolAddress((void**)&pK,   g_K);
    cudaGetSymbolAddress((void**)&pV,   g_V);
    cudaGetSymbolAddress((void**)&pHK,  g_HK);
    cudaGetSymbolAddress((void**)&pQH,  g_QH);
    cudaGetSymbolAddress((void**)&pPK,  g_PK);
    cudaGetSymbolAddress((void**)&pPQ,  g_PQ);
    cudaGetSymbolAddress((void**)&pCTX, g_CTX);
    cudaGetSymbolAddress((void**)&pATT, g_ATT);
    cudaGetSymbolAddress((void**)&pAO,  g_AO);
    cudaGetSymbolAddress((void**)&pH1,  g_H1);
    cudaGetSymbolAddress((void**)&pWT,  g_WT);
    cudaGetSymbolAddress((void**)&pBQK, g_BQK);
    cudaGetSymbolAddress((void**)&pBB2, g_BB2);

    cudaFuncSetAttribute(mma_gemm<0,0>, cudaFuncAttributeMaxDynamicSharedMemorySize, GEMM_SMEM);
    cudaFuncSetAttribute(mma_gemm<1,0>, cudaFuncAttributeMaxDynamicSharedMemorySize, GEMM_SMEM);
    cudaFuncSetAttribute(mma_gemm<1,1>, cudaFuncAttributeMaxDynamicSharedMemorySize, GEMM_SMEM);
    cudaFuncSetAttribute(mma_gemm<2,1>, cudaFuncAttributeMaxDynamicSharedMemorySize, GEMM_SMEM);
    cudaFuncSetAttribute(mma_gemm<3,1>, cudaFuncAttributeMaxDynamicSharedMemorySize, GEMM_SMEM);
    cudaFuncSetAttribute(mma_gemm<5,1>, cudaFuncAttributeMaxDynamicSharedMemorySize, GEMM_SMEM);
    cudaFuncSetAttribute(flash_attn, cudaFuncAttributeMaxDynamicSharedMemorySize, FL2_SMEM);

    // static side streams/events (created once; graph-capture safe)
    static cudaStream_t s1 = nullptr, s2 = nullptr;
    static cudaEvent_t evPrep = nullptr, evV = nullptr, evS2 = nullptr;
    if (!s1) {
        cudaStreamCreateWithFlags(&s1, cudaStreamNonBlocking);
        cudaStreamCreateWithFlags(&s2, cudaStreamNonBlocking);
        cudaEventCreateWithFlags(&evPrep, cudaEventDisableTiming);
        cudaEventCreateWithFlags(&evV,    cudaEventDisableTiming);
        cudaEventCreateWithFlags(&evS2,   cudaEventDisableTiming);
    }

    dim3 blk(256);

    // s2: pos projections with RAW weights (no prep dependency) — run parallel with prep
    dim3 gPosS(512 / 128, S / 128);
    mma_gemm<0,0><<<gPosS, blk, GEMM_SMEM, s2>>>(pos, Wpk, bpk, nullptr, nullptr, nullptr, pPK, nullptr, S, H, H);
    mma_gemm<0,0><<<gPosS, blk, GEMM_SMEM, s2>>>(pos, Wpq, bpq, nullptr, nullptr, nullptr, pPQ, nullptr, S, H, H);

    // default: prep (weights + biases)
    prep_kernel<<<(PR_END + 255) / 256, blk>>>(Wv, Wd, W1, W2,
                                               Wq, Wk, Wbk, Wbq,
                                               bq, bk, bbk, bbq);
    cudaEventRecord(evPrep, 0);
    cudaStreamWaitEvent(s1, evPrep, 0);
    cudaStreamWaitEvent(s2, evPrep, 0);

    dim3 gProj(512 / 128, BS / 128);
    mma_gemm<1,1><<<gProj, blk, GEMM_SMEM, s1>>>(vin, pWT + WT_V, bv, vin, nullptr, nullptr, pV, nullptr, BS, H, H);
    cudaEventRecord(evV, s1);

    dim3 gQK(1024 / 128, BS / 128);
    mma_gemm<5,1><<<gQK, blk, GEMM_SMEM, s2>>>(beha, pWT + WT_BKBQ, pBB2, nullptr, pPK, pPQ, pHK, pQH, BS, 1024, H);
    cudaEventRecord(evS2, s2);

    mma_gemm<3,1><<<gQK, blk, GEMM_SMEM>>>(x, pWT + WT_QK, pBQK, nullptr, nullptr, nullptr, pQ, pK, BS, 1024, H);

    // join before flash (needs Q,K,HK,QH,V)
    cudaStreamWaitEvent(0, evS2, 0);
    cudaStreamWaitEvent(0, evV, 0);

    // fused attention (q-tile 64, 128 threads)
    flash_attn<<<dim3(8, B * NH), dim3(128), FL2_SMEM>>>(iseq);

    mma_gemm<1,0><<<gProj, blk, GEMM_SMEM>>>(pCTX, pWT + WT_D, bd, x, nullptr, nullptr, pATT, nullptr, BS, H, H);
    ln_kernel<1><<<BS, blk>>>(pATT, ln_g, ln_b, pAO);

    dim3 gF1(INNER / 128, BS / 128);
    mma_gemm<2,1><<<gF1, blk, GEMM_SMEM>>>(pAO, pWT + WT_1, b1, nullptr, nullptr, nullptr, pH1, nullptr, BS, INNER, H);
    mma_gemm<1,0><<<gProj, blk, GEMM_SMEM>>>(pH1, pWT + WT_2, b2, pAO, nullptr, nullptr, pATT, nullptr, BS, H, INNER);
    ln_kernel<0><<<BS, blk>>>(pATT, ln2g, ln2b, out);
}